// round 14
// baseline (speedup 1.0000x reference)
#include <cuda_runtime.h>
#include <cuda_fp16.h>
#include <math.h>
#include <stdint.h>

// ---------------- problem constants ----------------
#define NROWS 8192
#define IN_F  512
#define RFF   2048
#define OUT_F 1000
#define OUT_P 1024
#define KBIG  (3*IN_F)                 // 1536: [Dhi|Dlo|Dhi] x [Whi|Whi|Wlo] (fp16)
#define INV_RFF_SCALAR (1.0f/32.0f)
#define MFF   25.0f

// ---------------- fp16 tiling ----------------
#define BM 128
#define BN 128
#define BKB 64
#define LDSH 72                        // halves per smem row (144 B)
#define AB_BYTES (128*LDSH*2)          // 18432
#define STAGE_BYTES_B (2*AB_BYTES)     // 36864
#define NSTAGE 3
#define NTH 128                        // 4 warps, 2x2 grid, 64x64 warp tiles
#define GRID_P 296

// tile queue: [0,1024) GEMM1, [1024,2048) GEMM2, [2048,2560) GEMM3
#define T_G2 1024
#define T_G3 2048
#define T_END 2560

// ---------------- device scratch ----------------
__device__ float  g_Phi[NROWS*RFF];
__device__ __half g_Phih [NROWS*RFF];
__device__ __half g_Phih2[NROWS*RFF];
__device__ __half g_covh [RFF*RFF];
__device__ __half g_lwh  [OUT_P*RFF];
__device__ __half g_Abh[NROWS*KBIG];
__device__ __half g_Bbh[RFF*KBIG];
__device__ float  g_diag_part[16*NROWS];
__device__ int    g_sync[2 + 64 + 64];  // [0]=tile ctr, [2..65]=done1, [66..129]=done2

// ---------------- helpers ----------------
__device__ __forceinline__ uint32_t smem_u32(const void* p) {
    uint32_t r;
    asm("{ .reg .u64 t; cvta.to.shared.u64 t, %1; cvt.u32.u64 %0, t; }" : "=r"(r) : "l"(p));
    return r;
}
__device__ __forceinline__ void cp16(uint32_t d, const void* s) {
    asm volatile("cp.async.cg.shared.global [%0], [%1], 16;" :: "r"(d), "l"(s));
}
__device__ __forceinline__ void cp_commit() { asm volatile("cp.async.commit_group;"); }
template <int N> __device__ __forceinline__ void cp_wait() {
    asm volatile("cp.async.wait_group %0;" :: "n"(N));
}
__device__ __forceinline__ void ldsm_x4(uint32_t* r, uint32_t a) {
    asm volatile("ldmatrix.sync.aligned.m8n8.x4.shared.b16 {%0,%1,%2,%3}, [%4];"
        : "=r"(r[0]), "=r"(r[1]), "=r"(r[2]), "=r"(r[3]) : "r"(a));
}
__device__ __forceinline__ void mma_f16(float* c, const uint32_t* a, const uint32_t* b) {
    asm volatile(
        "mma.sync.aligned.m16n8k16.row.col.f32.f16.f16.f32 "
        "{%0,%1,%2,%3}, {%4,%5,%6,%7}, {%8,%9}, {%0,%1,%2,%3};"
        : "+f"(c[0]), "+f"(c[1]), "+f"(c[2]), "+f"(c[3])
        : "r"(a[0]), "r"(a[1]), "r"(a[2]), "r"(a[3]), "r"(b[0]), "r"(b[1]));
}

// ---------------- fused prep kernel ----------------
#define PD_BLKS 16384
#define PW_BLKS 1024
#define PC_BLKS 4096
#define PL_BLKS 8192
__global__ void prep_all(const float* __restrict__ D, const float* __restrict__ W,
                         const float* __restrict__ cov, const float* __restrict__ lw,
                         __half* __restrict__ Abh, __half* __restrict__ Bbh,
                         __half* __restrict__ covh, __half* __restrict__ lwh)
{
    const int blk = blockIdx.x;
    const int tid = threadIdx.x;
    if (blk < PD_BLKS) {
        int idx = blk * 256 + tid;
        int r = idx >> 9, k = idx & (IN_F - 1);
        float x = D[idx];
        __half hi = __float2half(x);
        __half lo = __float2half(x - __half2float(hi));
        __half* p = Abh + (size_t)r * KBIG;
        p[k] = hi; p[IN_F + k] = lo; p[2 * IN_F + k] = hi;
    } else if (blk < PD_BLKS + PW_BLKS) {
        __shared__ float t[32][33];
        int wb = blk - PD_BLKS;
        int nb = (wb & 63) * 32, kb = (wb >> 6) * 32;
        int tx = tid & 31, ty0 = tid >> 5;
        #pragma unroll
        for (int i = 0; i < 32; i += 8) {
            int ty = ty0 + i;
            t[ty][tx] = W[(size_t)(kb + ty) * RFF + nb + tx];
        }
        __syncthreads();
        #pragma unroll
        for (int i = 0; i < 32; i += 8) {
            int ty = ty0 + i;
            int n = nb + ty, k = kb + tx;
            float x = t[tx][ty];
            __half hi = __float2half(x);
            __half lo = __float2half(x - __half2float(hi));
            __half* p = Bbh + (size_t)n * KBIG;
            p[k] = hi; p[IN_F + k] = hi; p[2 * IN_F + k] = lo;
        }
    } else if (blk < PD_BLKS + PW_BLKS + PC_BLKS) {
        int idx = ((blk - PD_BLKS - PW_BLKS) * 256 + tid) * 4;
        float4 v = *(const float4*)(cov + idx);
        __half2 a, b;
        a.x = __float2half(v.x); a.y = __float2half(v.y);
        b.x = __float2half(v.z); b.y = __float2half(v.w);
        *(__half2*)(covh + idx) = a;
        *(__half2*)(covh + idx + 2) = b;
    } else {
        int idx = (blk - PD_BLKS - PW_BLKS - PC_BLKS) * 256 + tid;
        int n = idx >> 11;
        lwh[idx] = (n < OUT_F) ? __float2half(lw[idx]) : __float2half(0.0f);
    }
}

// ---------------- fused persistent fp16 GEMM, 64x64 warp tiles ----------------
__global__ void __launch_bounds__(NTH, 2)
gp_fused(const __half* __restrict__ Abh, const __half* __restrict__ Bbh,
         const __half* __restrict__ Phih, const __half* __restrict__ Phih2,
         const __half* __restrict__ covh, const __half* __restrict__ lwh,
         float* __restrict__ Phi, __half* __restrict__ PhihW, __half* __restrict__ Phih2W,
         float* __restrict__ diagp,
         const float* __restrict__ biasb, const float* __restrict__ lb,
         float* __restrict__ outp, int* __restrict__ sync)
{
    extern __shared__ float dyn[];
    __shared__ int s_tile;
    const int tid = threadIdx.x;
    const int wid = tid >> 5, lane = tid & 31;
    const int g = lane >> 2, t = lane & 3;
    const int warpM = wid >> 1, warpN = wid & 1;   // 2x2 warp grid, 64x64 warp tiles
    const uint32_t sbase = smem_u32(dyn);
    int* done1 = sync + 2;
    int* done2 = sync + 66;

    const uint32_t aOff = (uint32_t)((((warpM * 64 + ((lane >> 3) & 1) * 8 + (lane & 7)) * LDSH)
                                      + ((lane >> 4) & 1) * 8) * 2);
    const uint32_t bOff = (uint32_t)(AB_BYTES
                                      + (((warpN * 64 + ((lane >> 4) & 1) * 8 + (lane & 7)) * LDSH
                                      + ((lane >> 3) & 1) * 8) * 2));

    for (;;) {
        if (tid == 0) s_tile = atomicAdd(sync, 1);
        __syncthreads();
        const int tile = s_tile;
        if (tile >= T_END) break;

        int mode, rowb, cblk;
        if (tile < T_G2)      { mode = 0; rowb = tile >> 4; cblk = tile & 15; }
        else if (tile < T_G3) { mode = 1; rowb = (tile - T_G2) >> 4; cblk = (tile - T_G2) & 15; }
        else                  { mode = 2; rowb = (tile - T_G3) >> 3; cblk = (tile - T_G3) & 7; }
        const int rowTile = rowb * BM, colTile = cblk * BN;

        const __half *Aptr, *Bptr;
        int K, nIter;
        if (mode == 0)      { Aptr = Abh;  Bptr = Bbh;  K = KBIG; nIter = KBIG / BKB; }
        else if (mode == 1) { Aptr = Phih; Bptr = covh; K = RFF;  nIter = (colTile + BN) / BKB; }
        else                { Aptr = Phih; Bptr = lwh;  K = RFF;  nIter = RFF / BKB; }

        // dependency spin
        if (mode == 1) {
            if (tid == 0) { while (atomicAdd(done1 + rowb, 0) < 16) __nanosleep(64); __threadfence(); }
            __syncthreads();
        } else if (mode == 2) {
            if (tid == 0) { while (atomicAdd(done2 + rowb, 0) < 16) __nanosleep(64); __threadfence(); }
            __syncthreads();
        }

        float acc[4][8][4];
        #pragma unroll
        for (int mt = 0; mt < 4; mt++)
            #pragma unroll
            for (int nt = 0; nt < 8; nt++)
                #pragma unroll
                for (int r = 0; r < 4; r++) acc[mt][nt][r] = 0.0f;

        #define ISSUEH(it, s) do {                                                 \
            const int _k0 = (it) * BKB;                                            \
            const __half* _as = (mode == 1 && _k0 < colTile) ? Phih2 : Aptr;       \
            _Pragma("unroll")                                                      \
            for (int j = 0; j < 8; j++) {                                          \
                int f = tid + NTH * j;                                             \
                int r = f >> 3, q = f & 7;                                         \
                uint32_t d = sbase + (uint32_t)(s) * STAGE_BYTES_B + (uint32_t)((r * LDSH + q * 8) * 2); \
                cp16(d, _as + (size_t)(rowTile + r) * K + _k0 + q * 8);            \
            }                                                                      \
            _Pragma("unroll")                                                      \
            for (int j = 0; j < 8; j++) {                                          \
                int f = tid + NTH * j;                                             \
                int r = f >> 3, q = f & 7;                                         \
                uint32_t d = sbase + (uint32_t)(s) * STAGE_BYTES_B + (uint32_t)(AB_BYTES + (r * LDSH + q * 8) * 2); \
                cp16(d, Bptr + (size_t)(colTile + r) * K + _k0 + q * 8);           \
            }                                                                      \
            cp_commit();                                                           \
        } while (0)

        ISSUEH(0, 0);
        ISSUEH(1, 1);

        int s = 0;
        for (int it = 0; it < nIter; ++it) {
            if (it + 1 < nIter) cp_wait<1>(); else cp_wait<0>();
            __syncthreads();
            if (it + 2 < nIter) ISSUEH(it + 2, (s + 2) % NSTAGE);

            const uint32_t aB = sbase + (uint32_t)s * STAGE_BYTES_B + aOff;
            const uint32_t bB = sbase + (uint32_t)s * STAGE_BYTES_B + bOff;
            #pragma unroll
            for (int kk = 0; kk < 4; kk++) {
                uint32_t af[4][4], bf[8][2];
                #pragma unroll
                for (int mt = 0; mt < 4; mt++)
                    ldsm_x4(af[mt], aB + (uint32_t)((mt * 16 * LDSH + kk * 16) * 2));
                #pragma unroll
                for (int np = 0; np < 4; np++) {
                    uint32_t r4[4];
                    ldsm_x4(r4, bB + (uint32_t)((np * 16 * LDSH + kk * 16) * 2));
                    bf[2 * np][0] = r4[0]; bf[2 * np][1] = r4[1];
                    bf[2 * np + 1][0] = r4[2]; bf[2 * np + 1][1] = r4[3];
                }
                #pragma unroll
                for (int mt = 0; mt < 4; mt++)
                    #pragma unroll
                    for (int nt = 0; nt < 8; nt++)
                        mma_f16(acc[mt][nt], af[mt], bf[nt]);
            }
            s = (s + 1 == NSTAGE) ? 0 : s + 1;
        }
        __syncthreads();

        // ---------------- epilogues ----------------
        if (mode == 0) {
            #pragma unroll
            for (int mt = 0; mt < 4; mt++)
                #pragma unroll
                for (int h = 0; h < 2; h++) {
                    const int R = rowTile + warpM * 64 + mt * 16 + g + h * 8;
                    float* op = Phi + (size_t)R * RFF;
                    __half* oph  = PhihW  + (size_t)R * RFF;
                    __half* oph2 = Phih2W + (size_t)R * RFF;
                    #pragma unroll
                    for (int nt = 0; nt < 8; nt++) {
                        const int C = colTile + warpN * 64 + nt * 8 + 2 * t;
                        float2 bb = *(const float2*)(biasb + C);
                        __half2 hh, hh2;
                        hh.x = __float2half(cosf(acc[mt][nt][h * 2 + 0] + bb.x) * INV_RFF_SCALAR);
                        hh.y = __float2half(cosf(acc[mt][nt][h * 2 + 1] + bb.y) * INV_RFF_SCALAR);
                        float2 o;
                        o.x = __half2float(hh.x);
                        o.y = __half2float(hh.y);
                        hh2.x = __float2half(2.0f * o.x);
                        hh2.y = __float2half(2.0f * o.y);
                        *(float2*)(op + C) = o;
                        *(__half2*)(oph + C) = hh;
                        *(__half2*)(oph2 + C) = hh2;
                    }
                }
            __threadfence();
            __syncthreads();
            if (tid == 0) atomicAdd(done1 + rowb, 1);
        } else if (mode == 1) {
            float* red = dyn;  // [128][2]
            #pragma unroll
            for (int mt = 0; mt < 4; mt++)
                #pragma unroll
                for (int h = 0; h < 2; h++) {
                    const int lr = warpM * 64 + mt * 16 + g + h * 8;
                    const float* pr = Phi + (size_t)(rowTile + lr) * RFF;
                    float sum = 0.0f;
                    #pragma unroll
                    for (int nt = 0; nt < 8; nt++) {
                        const int C = colTile + warpN * 64 + nt * 8 + 2 * t;
                        float2 p = __ldcg((const float2*)(pr + C));
                        sum = fmaf(acc[mt][nt][h * 2 + 0], p.x, sum);
                        sum = fmaf(acc[mt][nt][h * 2 + 1], p.y, sum);
                    }
                    sum += __shfl_xor_sync(0xffffffffu, sum, 1);
                    sum += __shfl_xor_sync(0xffffffffu, sum, 2);
                    if (t == 0) red[lr * 2 + warpN] = sum;
                }
            __syncthreads();
            {
                float sum = red[tid * 2 + 0] + red[tid * 2 + 1];
                diagp[(size_t)cblk * NROWS + rowTile + tid] = sum;
            }
            __threadfence();
            __syncthreads();
            if (tid == 0) atomicAdd(done2 + rowb, 1);
        } else {
            float* scale = dyn;  // [128]
            {
                float dg = 0.0f;
                #pragma unroll
                for (int p = 0; p < 16; p++) dg += __ldcg(diagp + (size_t)p * NROWS + rowTile + tid);
                scale[tid] = rsqrtf(1.0f + MFF * dg);
            }
            __syncthreads();
            #pragma unroll
            for (int mt = 0; mt < 4; mt++)
                #pragma unroll
                for (int h = 0; h < 2; h++) {
                    const int lr = warpM * 64 + mt * 16 + g + h * 8;
                    const int R = rowTile + lr;
                    const float sc = scale[lr];
                    float* op = outp + (size_t)R * OUT_F;
                    #pragma unroll
                    for (int nt = 0; nt < 8; nt++) {
                        const int C = colTile + warpN * 64 + nt * 8 + 2 * t;
                        if (C < OUT_F) {
                            float2 bb = *(const float2*)(lb + C);
                            float2 o;
                            o.x = (acc[mt][nt][h * 2 + 0] + bb.x) * sc;
                            o.y = (acc[mt][nt][h * 2 + 1] + bb.y) * sc;
                            *(float2*)(op + C) = o;
                        }
                    }
                }
            __syncthreads();
        }
        #undef ISSUEH
    }
}

// ---------------- host ----------------
extern "C" void kernel_launch(void* const* d_in, const int* in_sizes, int n_in,
                              void* d_out, int out_size)
{
    const float* D   = (const float*)d_in[0];
    const float* W   = (const float*)d_in[1];
    const float* b   = (const float*)d_in[2];
    const float* lw  = (const float*)d_in[3];
    const float* lb  = (const float*)d_in[4];
    const float* cov = (const float*)d_in[5];
    float* out = (float*)d_out;

    float *Phi, *diagp;
    __half *Phih, *Phih2, *covh, *lwh, *Abh, *Bbh;
    int* sync;
    cudaGetSymbolAddress((void**)&Phi,   g_Phi);
    cudaGetSymbolAddress((void**)&Phih,  g_Phih);
    cudaGetSymbolAddress((void**)&Phih2, g_Phih2);
    cudaGetSymbolAddress((void**)&covh,  g_covh);
    cudaGetSymbolAddress((void**)&lwh,   g_lwh);
    cudaGetSymbolAddress((void**)&Abh,   g_Abh);
    cudaGetSymbolAddress((void**)&Bbh,   g_Bbh);
    cudaGetSymbolAddress((void**)&diagp, g_diag_part);
    cudaGetSymbolAddress((void**)&sync,  g_sync);

    const int smem = NSTAGE * STAGE_BYTES_B;  // 110592 bytes
    cudaFuncSetAttribute(gp_fused, cudaFuncAttributeMaxDynamicSharedMemorySize, smem);

    cudaMemsetAsync(sync, 0, (2 + 64 + 64) * sizeof(int));

    prep_all<<<PD_BLKS + PW_BLKS + PC_BLKS + PL_BLKS, 256>>>(
        D, W, cov, lw, Abh, Bbh, covh, lwh);

    gp_fused<<<GRID_P, NTH, smem>>>(
        Abh, Bbh, Phih, Phih2, covh, lwh,
        Phi, Phih, Phih2, diagp, b, lb, out, sync);
}

// round 15
// speedup vs baseline: 1.1804x; 1.1804x over previous
#include <cuda_runtime.h>
#include <cuda_fp16.h>
#include <math.h>
#include <stdint.h>

// ---------------- problem constants ----------------
#define NROWS 8192
#define IN_F  512
#define RFF   2048
#define OUT_F 1000
#define OUT_P 1024
#define KBIG  (3*IN_F)                 // 1536: [Dhi|Dlo|Dhi] x [Whi|Whi|Wlo] (fp16)
#define INV_RFF_SCALAR (1.0f/32.0f)
#define MFF   25.0f

// ---------------- fp16 tiling (round-13 proven) ----------------
#define BM 128
#define BN 128
#define BKB 64
#define LDSH 72                        // halves per smem row (144 B)
#define AB_BYTES (128*LDSH*2)          // 18432
#define STAGE_BYTES_B (2*AB_BYTES)     // 36864
#define NSTAGE 3
#define NTH 256                        // 8 warps, 2x4 grid, 64x32 warp tiles
#define GRID_P 296

// tile queue: [0,1024) GEMM1, [1024,2048) GEMM2, [2048,2560) GEMM3
#define T_G2 1024
#define T_G3 2048
#define T_END 2560

// ---------------- device scratch ----------------
__device__ __half g_Phih [NROWS*RFF];              // fp16 Phi (the only Phi copy)
__device__ __half g_covh [RFF*RFF];                // fp16 cov
__device__ __half g_covh2[RFF*RFF];                // fp16 2*cov (exact)
__device__ __half g_lwh  [OUT_P*RFF];              // fp16 logit_w, zero-padded
__device__ __half g_Abh[NROWS*KBIG];
__device__ __half g_Bbh[RFF*KBIG];
__device__ float  g_diag_part[16*NROWS];
__device__ int    g_sync[2 + 64 + 64];  // [0]=tile ctr, [2..65]=done1, [66..129]=done2

// ---------------- helpers ----------------
__device__ __forceinline__ uint32_t smem_u32(const void* p) {
    uint32_t r;
    asm("{ .reg .u64 t; cvta.to.shared.u64 t, %1; cvt.u32.u64 %0, t; }" : "=r"(r) : "l"(p));
    return r;
}
__device__ __forceinline__ void cp16(uint32_t d, const void* s) {
    asm volatile("cp.async.cg.shared.global [%0], [%1], 16;" :: "r"(d), "l"(s));
}
__device__ __forceinline__ void cp_commit() { asm volatile("cp.async.commit_group;"); }
template <int N> __device__ __forceinline__ void cp_wait() {
    asm volatile("cp.async.wait_group %0;" :: "n"(N));
}
__device__ __forceinline__ void ldsm_x4(uint32_t* r, uint32_t a) {
    asm volatile("ldmatrix.sync.aligned.m8n8.x4.shared.b16 {%0,%1,%2,%3}, [%4];"
        : "=r"(r[0]), "=r"(r[1]), "=r"(r[2]), "=r"(r[3]) : "r"(a));
}
__device__ __forceinline__ void mma_f16(float* c, const uint32_t* a, const uint32_t* b) {
    asm volatile(
        "mma.sync.aligned.m16n8k16.row.col.f32.f16.f16.f32 "
        "{%0,%1,%2,%3}, {%4,%5,%6,%7}, {%8,%9}, {%0,%1,%2,%3};"
        : "+f"(c[0]), "+f"(c[1]), "+f"(c[2]), "+f"(c[3])
        : "r"(a[0]), "r"(a[1]), "r"(a[2]), "r"(a[3]), "r"(b[0]), "r"(b[1]));
}

// ---------------- fused prep kernel ----------------
#define PD_BLKS 16384
#define PW_BLKS 1024
#define PC_BLKS 4096
#define PL_BLKS 8192
__global__ void prep_all(const float* __restrict__ D, const float* __restrict__ W,
                         const float* __restrict__ cov, const float* __restrict__ lw,
                         __half* __restrict__ Abh, __half* __restrict__ Bbh,
                         __half* __restrict__ covh, __half* __restrict__ covh2,
                         __half* __restrict__ lwh)
{
    const int blk = blockIdx.x;
    const int tid = threadIdx.x;
    if (blk < PD_BLKS) {
        int idx = blk * 256 + tid;
        int r = idx >> 9, k = idx & (IN_F - 1);
        float x = D[idx];
        __half hi = __float2half(x);
        __half lo = __float2half(x - __half2float(hi));
        __half* p = Abh + (size_t)r * KBIG;
        p[k] = hi; p[IN_F + k] = lo; p[2 * IN_F + k] = hi;
    } else if (blk < PD_BLKS + PW_BLKS) {
        __shared__ float t[32][33];
        int wb = blk - PD_BLKS;
        int nb = (wb & 63) * 32, kb = (wb >> 6) * 32;
        int tx = tid & 31, ty0 = tid >> 5;
        #pragma unroll
        for (int i = 0; i < 32; i += 8) {
            int ty = ty0 + i;
            t[ty][tx] = W[(size_t)(kb + ty) * RFF + nb + tx];
        }
        __syncthreads();
        #pragma unroll
        for (int i = 0; i < 32; i += 8) {
            int ty = ty0 + i;
            int n = nb + ty, k = kb + tx;
            float x = t[tx][ty];
            __half hi = __float2half(x);
            __half lo = __float2half(x - __half2float(hi));
            __half* p = Bbh + (size_t)n * KBIG;
            p[k] = hi; p[IN_F + k] = hi; p[2 * IN_F + k] = lo;
        }
    } else if (blk < PD_BLKS + PW_BLKS + PC_BLKS) {
        int idx = ((blk - PD_BLKS - PW_BLKS) * 256 + tid) * 4;
        float4 v = *(const float4*)(cov + idx);
        __half2 a, b, a2, b2;
        a.x  = __float2half(v.x);        a.y  = __float2half(v.y);
        b.x  = __float2half(v.z);        b.y  = __float2half(v.w);
        a2.x = __float2half(2.0f * v.x); a2.y = __float2half(2.0f * v.y);
        b2.x = __float2half(2.0f * v.z); b2.y = __float2half(2.0f * v.w);
        *(__half2*)(covh + idx) = a;
        *(__half2*)(covh + idx + 2) = b;
        *(__half2*)(covh2 + idx) = a2;
        *(__half2*)(covh2 + idx + 2) = b2;
    } else {
        int idx = (blk - PD_BLKS - PW_BLKS - PC_BLKS) * 256 + tid;
        int n = idx >> 11;
        lwh[idx] = (n < OUT_F) ? __float2half(lw[idx]) : __float2half(0.0f);
    }
}

// ---------------- fused persistent fp16 GEMM (all three phases) ----------------
__global__ void __launch_bounds__(NTH, 2)
gp_fused(const __half* __restrict__ Abh, const __half* __restrict__ Bbh,
         const __half* __restrict__ Phih, const __half* __restrict__ covh,
         const __half* __restrict__ covh2, const __half* __restrict__ lwh,
         __half* __restrict__ PhihW, float* __restrict__ diagp,
         const float* __restrict__ biasb, const float* __restrict__ lb,
         float* __restrict__ outp, int* __restrict__ sync)
{
    extern __shared__ float dyn[];
    __shared__ int s_tile;
    const int tid = threadIdx.x;
    const int wid = tid >> 5, lane = tid & 31;
    const int g = lane >> 2, t = lane & 3;
    const int warpM = wid >> 2, warpN = wid & 3;   // 2x4 warp grid, 64x32 warp tiles
    const uint32_t sbase = smem_u32(dyn);
    int* done1 = sync + 2;
    int* done2 = sync + 66;

    const uint32_t aOff = (uint32_t)((((warpM * 64 + ((lane >> 3) & 1) * 8 + (lane & 7)) * LDSH)
                                      + ((lane >> 4) & 1) * 8) * 2);
    const uint32_t bOff = (uint32_t)(AB_BYTES
                                      + (((warpN * 32 + ((lane >> 4) & 1) * 8 + (lane & 7)) * LDSH
                                      + ((lane >> 3) & 1) * 8) * 2));

    for (;;) {
        if (tid == 0) s_tile = atomicAdd(sync, 1);
        __syncthreads();
        const int tile = s_tile;
        if (tile >= T_END) break;

        int mode, rowb, cblk;
        if (tile < T_G2)      { mode = 0; rowb = tile >> 4; cblk = tile & 15; }
        else if (tile < T_G3) { mode = 1; rowb = (tile - T_G2) >> 4; cblk = (tile - T_G2) & 15; }
        else                  { mode = 2; rowb = (tile - T_G3) >> 3; cblk = (tile - T_G3) & 7; }
        const int rowTile = rowb * BM, colTile = cblk * BN;

        const __half *Aptr, *Bptr;
        int K, nIter;
        if (mode == 0)      { Aptr = Abh;  Bptr = Bbh;  K = KBIG; nIter = KBIG / BKB; }
        else if (mode == 1) { Aptr = Phih; Bptr = covh; K = RFF;  nIter = (colTile + BN) / BKB; }
        else                { Aptr = Phih; Bptr = lwh;  K = RFF;  nIter = RFF / BKB; }

        // dependency spin (release/acquire via threadfence + atomics)
        if (mode == 1) {
            if (tid == 0) { while (atomicAdd(done1 + rowb, 0) < 16) __nanosleep(64); __threadfence(); }
            __syncthreads();
        } else if (mode == 2) {
            if (tid == 0) { while (atomicAdd(done2 + rowb, 0) < 16) __nanosleep(64); __threadfence(); }
            __syncthreads();
        }

        float acc[4][4][4];
        #pragma unroll
        for (int mt = 0; mt < 4; mt++)
            #pragma unroll
            for (int nt = 0; nt < 4; nt++)
                #pragma unroll
                for (int r = 0; r < 4; r++) acc[mt][nt][r] = 0.0f;

        #define ISSUEH(it, s) do {                                                 \
            const int _k0 = (it) * BKB;                                            \
            const __half* _bs = (mode == 1 && _k0 < colTile) ? covh2 : Bptr;       \
            _Pragma("unroll")                                                      \
            for (int j = 0; j < 4; j++) {                                          \
                int f = tid + NTH * j;                                             \
                int r = f >> 3, q = f & 7;                                         \
                uint32_t d = sbase + (uint32_t)(s) * STAGE_BYTES_B + (uint32_t)((r * LDSH + q * 8) * 2); \
                cp16(d, Aptr + (size_t)(rowTile + r) * K + _k0 + q * 8);           \
            }                                                                      \
            _Pragma("unroll")                                                      \
            for (int j = 0; j < 4; j++) {                                          \
                int f = tid + NTH * j;                                             \
                int r = f >> 3, q = f & 7;                                         \
                uint32_t d = sbase + (uint32_t)(s) * STAGE_BYTES_B + (uint32_t)(AB_BYTES + (r * LDSH + q * 8) * 2); \
                cp16(d, _bs + (size_t)(colTile + r) * K + _k0 + q * 8);            \
            }                                                                      \
            cp_commit();                                                           \
        } while (0)

        ISSUEH(0, 0);
        ISSUEH(1, 1);

        int s = 0;
        for (int it = 0; it < nIter; ++it) {
            if (it + 1 < nIter) cp_wait<1>(); else cp_wait<0>();
            __syncthreads();
            if (it + 2 < nIter) ISSUEH(it + 2, (s + 2) % NSTAGE);

            const uint32_t aB = sbase + (uint32_t)s * STAGE_BYTES_B + aOff;
            const uint32_t bB = sbase + (uint32_t)s * STAGE_BYTES_B + bOff;
            #pragma unroll
            for (int kk = 0; kk < 4; kk++) {
                uint32_t af[4][4], bf[4][2];
                #pragma unroll
                for (int mt = 0; mt < 4; mt++)
                    ldsm_x4(af[mt], aB + (uint32_t)((mt * 16 * LDSH + kk * 16) * 2));
                #pragma unroll
                for (int np = 0; np < 2; np++) {
                    uint32_t r4[4];
                    ldsm_x4(r4, bB + (uint32_t)((np * 16 * LDSH + kk * 16) * 2));
                    bf[2 * np][0] = r4[0]; bf[2 * np][1] = r4[1];
                    bf[2 * np + 1][0] = r4[2]; bf[2 * np + 1][1] = r4[3];
                }
                #pragma unroll
                for (int mt = 0; mt < 4; mt++)
                    #pragma unroll
                    for (int nt = 0; nt < 4; nt++)
                        mma_f16(acc[mt][nt], af[mt], bf[nt]);
            }
            s = (s + 1 == NSTAGE) ? 0 : s + 1;
        }
        __syncthreads();

        // ---------------- epilogues ----------------
        if (mode == 0) {
            #pragma unroll
            for (int mt = 0; mt < 4; mt++)
                #pragma unroll
                for (int h = 0; h < 2; h++) {
                    const int R = rowTile + warpM * 64 + mt * 16 + g + h * 8;
                    __half* oph = PhihW + (size_t)R * RFF;
                    #pragma unroll
                    for (int nt = 0; nt < 4; nt++) {
                        const int C = colTile + warpN * 32 + nt * 8 + 2 * t;
                        float2 bb = *(const float2*)(biasb + C);
                        __half2 hh;
                        hh.x = __float2half(cosf(acc[mt][nt][h * 2 + 0] + bb.x) * INV_RFF_SCALAR);
                        hh.y = __float2half(cosf(acc[mt][nt][h * 2 + 1] + bb.y) * INV_RFF_SCALAR);
                        *(__half2*)(oph + C) = hh;
                    }
                }
            __threadfence();
            __syncthreads();
            if (tid == 0) atomicAdd(done1 + rowb, 1);
        } else if (mode == 1) {
            float* red = dyn;  // [128][4]
            #pragma unroll
            for (int mt = 0; mt < 4; mt++)
                #pragma unroll
                for (int h = 0; h < 2; h++) {
                    const int lr = warpM * 64 + mt * 16 + g + h * 8;
                    const __half* pr = Phih + (size_t)(rowTile + lr) * RFF;
                    float sum = 0.0f;
                    #pragma unroll
                    for (int nt = 0; nt < 4; nt++) {
                        const int C = colTile + warpN * 32 + nt * 8 + 2 * t;
                        __half2 p = __ldcg((const __half2*)(pr + C));
                        sum = fmaf(acc[mt][nt][h * 2 + 0], __half2float(p.x), sum);
                        sum = fmaf(acc[mt][nt][h * 2 + 1], __half2float(p.y), sum);
                    }
                    sum += __shfl_xor_sync(0xffffffffu, sum, 1);
                    sum += __shfl_xor_sync(0xffffffffu, sum, 2);
                    if (t == 0) red[lr * 4 + warpN] = sum;
                }
            __syncthreads();
            if (tid < 128) {
                float sum = red[tid * 4 + 0] + red[tid * 4 + 1] + red[tid * 4 + 2] + red[tid * 4 + 3];
                diagp[(size_t)cblk * NROWS + rowTile + tid] = sum;
            }
            __threadfence();
            __syncthreads();
            if (tid == 0) atomicAdd(done2 + rowb, 1);
        } else {
            float* scale = dyn;  // [128]
            if (tid < 128) {
                float dg = 0.0f;
                #pragma unroll
                for (int p = 0; p < 16; p++) dg += __ldcg(diagp + (size_t)p * NROWS + rowTile + tid);
                scale[tid] = rsqrtf(1.0f + MFF * dg);
            }
            __syncthreads();
            #pragma unroll
            for (int mt = 0; mt < 4; mt++)
                #pragma unroll
                for (int h = 0; h < 2; h++) {
                    const int lr = warpM * 64 + mt * 16 + g + h * 8;
                    const int R = rowTile + lr;
                    const float sc = scale[lr];
                    float* op = outp + (size_t)R * OUT_F;
                    #pragma unroll
                    for (int nt = 0; nt < 4; nt++) {
                        const int C = colTile + warpN * 32 + nt * 8 + 2 * t;
                        if (C < OUT_F) {
                            float2 bb = *(const float2*)(lb + C);
                            float2 o;
                            o.x = (acc[mt][nt][h * 2 + 0] + bb.x) * sc;
                            o.y = (acc[mt][nt][h * 2 + 1] + bb.y) * sc;
                            *(float2*)(op + C) = o;
                        }
                    }
                }
            __syncthreads();
        }
        #undef ISSUEH
    }
}

// ---------------- host ----------------
extern "C" void kernel_launch(void* const* d_in, const int* in_sizes, int n_in,
                              void* d_out, int out_size)
{
    const float* D   = (const float*)d_in[0];
    const float* W   = (const float*)d_in[1];
    const float* b   = (const float*)d_in[2];
    const float* lw  = (const float*)d_in[3];
    const float* lb  = (const float*)d_in[4];
    const float* cov = (const float*)d_in[5];
    float* out = (float*)d_out;

    float *diagp;
    __half *Phih, *covh, *covh2, *lwh, *Abh, *Bbh;
    int* sync;
    cudaGetSymbolAddress((void**)&Phih,  g_Phih);
    cudaGetSymbolAddress((void**)&covh,  g_covh);
    cudaGetSymbolAddress((void**)&covh2, g_covh2);
    cudaGetSymbolAddress((void**)&lwh,   g_lwh);
    cudaGetSymbolAddress((void**)&Abh,   g_Abh);
    cudaGetSymbolAddress((void**)&Bbh,   g_Bbh);
    cudaGetSymbolAddress((void**)&diagp, g_diag_part);
    cudaGetSymbolAddress((void**)&sync,  g_sync);

    const int smem = NSTAGE * STAGE_BYTES_B;  // 110592 bytes
    cudaFuncSetAttribute(gp_fused, cudaFuncAttributeMaxDynamicSharedMemorySize, smem);

    cudaMemsetAsync(sync, 0, (2 + 64 + 64) * sizeof(int));

    prep_all<<<PD_BLKS + PW_BLKS + PC_BLKS + PL_BLKS, 256>>>(
        D, W, cov, lw, Abh, Bbh, covh, covh2, lwh);

    gp_fused<<<GRID_P, NTH, smem>>>(
        Abh, Bbh, Phih, covh, covh2, lwh,
        Phih, diagp, b, lb, out, sync);
}